// round 3
// baseline (speedup 1.0000x reference)
#include <cuda_runtime.h>
#include <cstdint>
#include <math.h>

// ---------------------------------------------------------------------------
// TemporalAttention: B=4, S=2048, D=512, H=8, hd=64, MAX_LAG=10
// Outputs: out [B,S,D] then attn_mean [B,S,S], both fp32, concatenated.
//
// Structure: bias is -1e9 for lag>10; causal mask for j>i. exp underflows to
// exactly 0 in fp32 outside the band, matching the reference bit-for-bit in
// those positions. So attention is an 11-wide banded causal attention.
// ---------------------------------------------------------------------------

#define BATCH   4
#define SEQ     2048
#define DMODEL  512
#define NHEADS  8
#define HDIM    64
#define MAXLAG  10

#define MTOT (BATCH * SEQ)          // 8192 rows for projections

// Scratch (allocation-free rule: __device__ globals)
__device__ float g_Q[MTOT * DMODEL];
__device__ float g_K[MTOT * DMODEL];
__device__ float g_V[MTOT * DMODEL];
__device__ float g_ctx[MTOT * DMODEL];

// ---------------------------------------------------------------------------
// SGEMM: C[M,N] = A[M,K] @ B[K,N] + bias[N], row-major, fp32.
// Tile 128x128x8, 256 threads, 8x8 per-thread register blocking.
// M=8192, N=512, K=512 -> all divisible, no bounds checks.
// ---------------------------------------------------------------------------
#define BM 128
#define BN 128
#define BKK 8
#define TM 8
#define TN 8

__global__ __launch_bounds__(256) void sgemm_bias(
    const float* __restrict__ A, const float* __restrict__ B,
    const float* __restrict__ bias, float* __restrict__ C,
    int M, int N, int K)
{
    __shared__ float As[BKK][BM];
    __shared__ float Bs[BKK][BN];

    const int tid  = threadIdx.x;
    const int cRow = blockIdx.y * BM;
    const int cCol = blockIdx.x * BN;

    // A tile loads: 128x8 = 1024 floats = 256 float4 (one per thread)
    const int aRow = tid >> 1;            // 0..127
    const int aCol = (tid & 1) << 2;      // 0 or 4
    // B tile loads: 8x128 = 1024 floats
    const int bRow = tid >> 5;            // 0..7
    const int bCol = (tid & 31) << 2;     // 0..124

    const int tr = (tid >> 4) * TM;       // 0..120
    const int tc = (tid & 15) * TN;       // 0..120

    float acc[TM][TN] = {};
    float regM[TM], regN[TN];

    const float* Aptr = A + (size_t)cRow * K;
    const float* Bptr = B + cCol;

    for (int k0 = 0; k0 < K; k0 += BKK) {
        float4 a4 = *reinterpret_cast<const float4*>(Aptr + (size_t)aRow * K + k0 + aCol);
        As[aCol + 0][aRow] = a4.x;
        As[aCol + 1][aRow] = a4.y;
        As[aCol + 2][aRow] = a4.z;
        As[aCol + 3][aRow] = a4.w;
        float4 b4 = *reinterpret_cast<const float4*>(Bptr + (size_t)(k0 + bRow) * N + bCol);
        *reinterpret_cast<float4*>(&Bs[bRow][bCol]) = b4;
        __syncthreads();

#pragma unroll
        for (int k = 0; k < BKK; k++) {
#pragma unroll
            for (int m = 0; m < TM; m++) regM[m] = As[k][tr + m];
#pragma unroll
            for (int n = 0; n < TN; n++) regN[n] = Bs[k][tc + n];
#pragma unroll
            for (int m = 0; m < TM; m++)
#pragma unroll
                for (int n = 0; n < TN; n++)
                    acc[m][n] += regM[m] * regN[n];
        }
        __syncthreads();
    }

#pragma unroll
    for (int m = 0; m < TM; m++) {
#pragma unroll
        for (int n = 0; n < TN; n += 4) {
            float4 o;
            o.x = acc[m][n + 0] + bias[cCol + tc + n + 0];
            o.y = acc[m][n + 1] + bias[cCol + tc + n + 1];
            o.z = acc[m][n + 2] + bias[cCol + tc + n + 2];
            o.w = acc[m][n + 3] + bias[cCol + tc + n + 3];
            *reinterpret_cast<float4*>(&C[(size_t)(cRow + tr + m) * N + cCol + tc + n]) = o;
        }
    }
}

// ---------------------------------------------------------------------------
// Banded causal attention.
// Grid: one block per (b, i) = 8192 blocks. 256 threads = 8 warps, warp h
// handles head h. Window j in [max(0, i-10), i], <= 11 entries.
// Writes ctx[b,i,:] and the banded entries of attn_mean (rest zeroed by
// a prior memset).
// ---------------------------------------------------------------------------
__global__ __launch_bounds__(256) void attn_banded(
    const float* __restrict__ Q, const float* __restrict__ K,
    const float* __restrict__ V, const float* __restrict__ td,
    float* __restrict__ ctx, float* __restrict__ attn_mean)
{
    const int bi = blockIdx.x;       // b*SEQ + i
    const int b  = bi >> 11;         // SEQ = 2048
    const int i  = bi & (SEQ - 1);
    const int tid = threadIdx.x;
    const int h = tid >> 5;
    const int l = tid & 31;

    __shared__ float s_d[MAXLAG + 1];
    __shared__ float s_attn[NHEADS][MAXLAG + 1];

    if (tid <= MAXLAG) {
        float x = td[tid];
        // stable softplus
        float sp = (x > 20.f) ? x : log1pf(expf(x));
        s_d[tid] = -logf(sp + 1e-8f);
    }
    __syncthreads();

    const int jstart = (i > MAXLAG) ? (i - MAXLAG) : 0;
    const int nj = i - jstart + 1;   // 1..11

    const float2* qp = reinterpret_cast<const float2*>(Q + (size_t)bi * DMODEL + h * HDIM);
    const float2 q2 = qp[l];

    float sc[MAXLAG + 1];
#pragma unroll
    for (int jj = 0; jj <= MAXLAG; jj++) {
        if (jj < nj) {
            const int j = jstart + jj;
            const float2* kp = reinterpret_cast<const float2*>(
                K + ((size_t)b * SEQ + j) * DMODEL + h * HDIM);
            const float2 k2 = kp[l];
            float dot = q2.x * k2.x + q2.y * k2.y;
#pragma unroll
            for (int off = 16; off; off >>= 1)
                dot += __shfl_xor_sync(0xffffffffu, dot, off);
            sc[jj] = dot * 0.125f + s_d[i - j];   // 1/sqrt(64)
        } else {
            sc[jj] = -1e30f;
        }
    }

    // softmax over <= 11 entries (all lanes hold identical reduced values)
    float mx = sc[0];
#pragma unroll
    for (int jj = 1; jj <= MAXLAG; jj++) mx = fmaxf(mx, sc[jj]);
    float sum = 0.f;
#pragma unroll
    for (int jj = 0; jj <= MAXLAG; jj++) {
        sc[jj] = expf(sc[jj] - mx);   // invalid entries -> exp(-huge) = 0
        sum += sc[jj];
    }
    const float inv = 1.f / sum;

    float c0 = 0.f, c1 = 0.f;
#pragma unroll
    for (int jj = 0; jj <= MAXLAG; jj++) {
        if (jj < nj) {
            const float p = sc[jj] * inv;
            const int j = jstart + jj;
            const float2* vp = reinterpret_cast<const float2*>(
                V + ((size_t)b * SEQ + j) * DMODEL + h * HDIM);
            const float2 v2 = vp[l];
            c0 = fmaf(p, v2.x, c0);
            c1 = fmaf(p, v2.y, c1);
            if (l == 0) s_attn[h][jj] = p;
        }
    }

    float2* cp = reinterpret_cast<float2*>(ctx + (size_t)bi * DMODEL + h * HDIM);
    cp[l] = make_float2(c0, c1);

    __syncthreads();
    if (tid < nj) {
        float a = 0.f;
#pragma unroll
        for (int hh = 0; hh < NHEADS; hh++) a += s_attn[hh][tid];
        attn_mean[(size_t)b * SEQ * SEQ + (size_t)i * SEQ + jstart + tid] = a * (1.f / NHEADS);
    }
}

// ---------------------------------------------------------------------------
extern "C" void kernel_launch(void* const* d_in, const int* in_sizes, int n_in,
                              void* d_out, int out_size)
{
    const float* x  = (const float*)d_in[0];
    const float* Wq = (const float*)d_in[1];
    const float* bq = (const float*)d_in[2];
    const float* Wk = (const float*)d_in[3];
    const float* bk = (const float*)d_in[4];
    const float* Wv = (const float*)d_in[5];
    const float* bv = (const float*)d_in[6];
    const float* Wo = (const float*)d_in[7];
    const float* bo = (const float*)d_in[8];
    const float* td = (const float*)d_in[9];

    float* out_ptr  = (float*)d_out;                                  // [B,S,D]
    float* attn_ptr = out_ptr + (size_t)BATCH * SEQ * DMODEL;         // [B,S,S]

    float* Qs;  cudaGetSymbolAddress((void**)&Qs,  g_Q);
    float* Ks;  cudaGetSymbolAddress((void**)&Ks,  g_K);
    float* Vs;  cudaGetSymbolAddress((void**)&Vs,  g_V);
    float* Cs;  cudaGetSymbolAddress((void**)&Cs,  g_ctx);

    dim3 gGemm(DMODEL / BN, MTOT / BM);   // (4, 64)
    dim3 tGemm(256);

    sgemm_bias<<<gGemm, tGemm>>>(x, Wq, bq, Qs, MTOT, DMODEL, DMODEL);
    sgemm_bias<<<gGemm, tGemm>>>(x, Wk, bk, Ks, MTOT, DMODEL, DMODEL);
    sgemm_bias<<<gGemm, tGemm>>>(x, Wv, bv, Vs, MTOT, DMODEL, DMODEL);

    // Zero the attn_mean region (band writes land on top of it)
    cudaMemsetAsync(attn_ptr, 0, (size_t)BATCH * SEQ * SEQ * sizeof(float), 0);

    attn_banded<<<MTOT, 256>>>(Qs, Ks, Vs, td, Cs, attn_ptr);

    sgemm_bias<<<gGemm, tGemm>>>(Cs, Wo, bo, out_ptr, MTOT, DMODEL, DMODEL);
}

// round 5
// speedup vs baseline: 2.0323x; 2.0323x over previous
#include <cuda_runtime.h>
#include <cuda_bf16.h>
#include <cstdint>
#include <math.h>

// ---------------------------------------------------------------------------
// TemporalAttention: B=4, S=2048, D=512, H=8, hd=64, MAX_LAG=10
// R4: tcgen05 PTX is rejected by this harness's compute_100 PTX target, so the
// projections use warp-level mma.sync bf16 (3-term split => fp32-accurate),
// ldmatrix + cp.async double-buffered pipeline. Banded attention unchanged.
// ---------------------------------------------------------------------------

#define BATCH   4
#define SEQ     2048
#define DMODEL  512
#define NHEADS  8
#define HDIM    64
#define MAXLAG  10
#define MTOT    (BATCH * SEQ)        // 8192

// ---------------- scratch (__device__ globals; no allocs allowed) ----------
__device__ __nv_bfloat16 g_Xhi[MTOT * DMODEL];
__device__ __nv_bfloat16 g_Xlo[MTOT * DMODEL];
__device__ __nv_bfloat16 g_Chi[MTOT * DMODEL];
__device__ __nv_bfloat16 g_Clo[MTOT * DMODEL];
__device__ __nv_bfloat16 g_WT [4 * 2 * DMODEL * DMODEL]; // [w][hi/lo][n*K+k]
__device__ float g_Q[MTOT * DMODEL];
__device__ float g_K[MTOT * DMODEL];
__device__ float g_V[MTOT * DMODEL];

// ---------------- helpers ---------------------------------------------------
__device__ __forceinline__ uint32_t smem_u32(const void* p) {
    uint32_t a;
    asm("{ .reg .u64 t; cvta.to.shared.u64 t, %1; cvt.u32.u64 %0, t; }"
        : "=r"(a) : "l"(p));
    return a;
}
__device__ __forceinline__ void cpasync16(uint32_t sdst, const void* gsrc) {
    asm volatile("cp.async.cg.shared.global [%0], [%1], 16;"
                 :: "r"(sdst), "l"(gsrc));
}
__device__ __forceinline__ void ldsm_x4(uint32_t* r, uint32_t addr) {
    asm volatile("ldmatrix.sync.aligned.m8n8.x4.shared.b16 {%0,%1,%2,%3}, [%4];"
                 : "=r"(r[0]), "=r"(r[1]), "=r"(r[2]), "=r"(r[3]) : "r"(addr));
}
__device__ __forceinline__ void ldsm_x2(uint32_t* r, uint32_t addr) {
    asm volatile("ldmatrix.sync.aligned.m8n8.x2.shared.b16 {%0,%1}, [%2];"
                 : "=r"(r[0]), "=r"(r[1]) : "r"(addr));
}
__device__ __forceinline__ void mma_bf16(float* d, const uint32_t* a,
                                         const uint32_t* b) {
    asm volatile(
        "mma.sync.aligned.m16n8k16.row.col.f32.bf16.bf16.f32 "
        "{%0,%1,%2,%3}, {%4,%5,%6,%7}, {%8,%9}, {%0,%1,%2,%3};"
        : "+f"(d[0]), "+f"(d[1]), "+f"(d[2]), "+f"(d[3])
        : "r"(a[0]), "r"(a[1]), "r"(a[2]), "r"(a[3]), "r"(b[0]), "r"(b[1]));
}

__device__ __forceinline__ void split2(float a, float b, __nv_bfloat162& hi,
                                       __nv_bfloat162& lo) {
    __nv_bfloat16 ha = __float2bfloat16_rn(a);
    __nv_bfloat16 hb = __float2bfloat16_rn(b);
    __nv_bfloat16 la = __float2bfloat16_rn(a - __bfloat162float(ha));
    __nv_bfloat16 lb = __float2bfloat16_rn(b - __bfloat162float(hb));
    hi = __nv_bfloat162(ha, hb);
    lo = __nv_bfloat162(la, lb);
}

// ---------------------------------------------------------------------------
// conversions
// ---------------------------------------------------------------------------
__global__ __launch_bounds__(256) void convert_split(
    const float* __restrict__ X, __nv_bfloat16* __restrict__ hi,
    __nv_bfloat16* __restrict__ lo, int n4)
{
    int i = blockIdx.x * blockDim.x + threadIdx.x;
    if (i >= n4) return;
    float4 v = reinterpret_cast<const float4*>(X)[i];
    __nv_bfloat162 h0, l0, h1, l1;
    split2(v.x, v.y, h0, l0);
    split2(v.z, v.w, h1, l1);
    reinterpret_cast<__nv_bfloat162*>(hi)[2 * i]     = h0;
    reinterpret_cast<__nv_bfloat162*>(hi)[2 * i + 1] = h1;
    reinterpret_cast<__nv_bfloat162*>(lo)[2 * i]     = l0;
    reinterpret_cast<__nv_bfloat162*>(lo)[2 * i + 1] = l1;
}

__global__ __launch_bounds__(256) void wsplitT(
    const float* __restrict__ W, __nv_bfloat16* __restrict__ hiT,
    __nv_bfloat16* __restrict__ loT)
{
    __shared__ float tile[32][33];
    const int n0 = blockIdx.x * 32, k0 = blockIdx.y * 32;
    const int tx = threadIdx.x, ty = threadIdx.y;   // (32, 8)
#pragma unroll
    for (int r = 0; r < 32; r += 8)
        tile[ty + r][tx] = W[(size_t)(k0 + ty + r) * DMODEL + n0 + tx];
    __syncthreads();
#pragma unroll
    for (int r = 0; r < 32; r += 8) {
        float v = tile[tx][ty + r];
        __nv_bfloat16 h = __float2bfloat16_rn(v);
        __nv_bfloat16 l = __float2bfloat16_rn(v - __bfloat162float(h));
        size_t idx = (size_t)(n0 + ty + r) * DMODEL + k0 + tx;
        hiT[idx] = h;
        loT[idx] = l;
    }
}

// ---------------------------------------------------------------------------
// bf16 3-term-split GEMM via mma.sync:
//   C[M,N] = Ahi@Bhi^T + Alo@Bhi^T + Ahi@Blo^T + bias
// A*: [MTOT][512] bf16 row-major. B*T: [512(n)][512(k)] bf16 (K contiguous).
// Tile 128x128, BK=32 bf16, 256 thr = 2x4 warps (warp tile 64x32).
// cp.async 2-stage pipeline, smem rows padded to 80B (ldmatrix conflict-free).
// ---------------------------------------------------------------------------
#define BK        32
#define ROWB      80                    // 64B data + 16B pad
#define TILEB     (128 * ROWB)          // 10240 per tile
#define STAGEB    (4 * TILEB)           // Ahi,Alo,Bhi,Blo = 40960
#define GSMEM_DYN (2 * STAGEB)          // 81920
#define NKT       (DMODEL / BK)         // 16

__device__ __forceinline__ void issue_stage(
    uint32_t sbase, const char* pA_hi, const char* pA_lo,
    const char* pB_hi, const char* pB_lo, int kt, int tid)
{
    const size_t koff = (size_t)kt * 64;      // BK*2 bytes
    const char* gsrc[4] = { pA_hi, pA_lo, pB_hi, pB_lo };
#pragma unroll
    for (int t = 0; t < 4; t++) {
        uint32_t sdst = sbase + t * TILEB;
#pragma unroll
        for (int q = 0; q < 2; q++) {
            int chunk = tid + q * 256;        // 0..511
            int row = chunk >> 2, c = chunk & 3;
            cpasync16(sdst + row * ROWB + c * 16,
                      gsrc[t] + (size_t)row * 1024 + koff + c * 16);
        }
    }
}

__global__ __launch_bounds__(256) void gemm_bf16x3(
    const __nv_bfloat16* __restrict__ Ahi, const __nv_bfloat16* __restrict__ Alo,
    const __nv_bfloat16* __restrict__ BhiT, const __nv_bfloat16* __restrict__ BloT,
    const float* __restrict__ bias, float* __restrict__ C)
{
    extern __shared__ char dsm[];
    const int tid = threadIdx.x;
    const int wid = tid >> 5;
    const int l   = tid & 31;
    const int wm  = wid >> 2;          // 0..1
    const int wn  = wid & 3;           // 0..3
    const int cRow = blockIdx.y * 128;
    const int cCol = blockIdx.x * 128;

    const uint32_t sbase = smem_u32(dsm);

    const char* pAhi = reinterpret_cast<const char*>(Ahi + (size_t)cRow * DMODEL);
    const char* pAlo = reinterpret_cast<const char*>(Alo + (size_t)cRow * DMODEL);
    const char* pBhi = reinterpret_cast<const char*>(BhiT + (size_t)cCol * DMODEL);
    const char* pBlo = reinterpret_cast<const char*>(BloT + (size_t)cCol * DMODEL);

    float acc[4][4][4] = {};

    // prologue: stage 0
    issue_stage(sbase, pAhi, pAlo, pBhi, pBlo, 0, tid);
    asm volatile("cp.async.commit_group;" ::: "memory");

    // precomputed ldmatrix lane offsets
    const int aRow = wm * 64 + (l & 15);           // + mi*16
    const int aChk = (l >> 4);                     // + 2*ks
    const int bRow = wn * 32 + (l & 7);            // + ni*8
    const int bChk = ((l >> 3) & 1);               // + 2*ks

    for (int kt = 0; kt < NKT; kt++) {
        if (kt + 1 < NKT)
            issue_stage(sbase + ((kt + 1) & 1) * STAGEB,
                        pAhi, pAlo, pBhi, pBlo, kt + 1, tid);
        asm volatile("cp.async.commit_group;" ::: "memory");
        asm volatile("cp.async.wait_group 1;" ::: "memory");
        __syncthreads();

        const uint32_t st = sbase + (kt & 1) * STAGEB;
        const uint32_t sAhi = st,             sAlo = st + TILEB;
        const uint32_t sBhi = st + 2 * TILEB, sBlo = st + 3 * TILEB;

#pragma unroll
        for (int ks = 0; ks < 2; ks++) {
            uint32_t ah[4][4], al[4][4], bh[4][2], bl[4][2];
#pragma unroll
            for (int mi = 0; mi < 4; mi++) {
                uint32_t off = (aRow + mi * 16) * ROWB + (aChk + 2 * ks) * 16;
                ldsm_x4(ah[mi], sAhi + off);
                ldsm_x4(al[mi], sAlo + off);
            }
#pragma unroll
            for (int ni = 0; ni < 4; ni++) {
                uint32_t off = (bRow + ni * 8) * ROWB + (bChk + 2 * ks) * 16;
                ldsm_x2(bh[ni], sBhi + off);
                ldsm_x2(bl[ni], sBlo + off);
            }
#pragma unroll
            for (int mi = 0; mi < 4; mi++)
#pragma unroll
                for (int ni = 0; ni < 4; ni++) {
                    mma_bf16(acc[mi][ni], ah[mi], bh[ni]);
                    mma_bf16(acc[mi][ni], al[mi], bh[ni]);
                    mma_bf16(acc[mi][ni], ah[mi], bl[ni]);
                }
        }
        __syncthreads();
    }

    // epilogue: fragment -> C (+bias)
#pragma unroll
    for (int mi = 0; mi < 4; mi++) {
        const int r0 = cRow + wm * 64 + mi * 16 + (l >> 2);
#pragma unroll
        for (int ni = 0; ni < 4; ni++) {
            const int col = cCol + wn * 32 + ni * 8 + 2 * (l & 3);
            const float b0 = bias[col], b1 = bias[col + 1];
            float2 v0 = { acc[mi][ni][0] + b0, acc[mi][ni][1] + b1 };
            float2 v1 = { acc[mi][ni][2] + b0, acc[mi][ni][3] + b1 };
            *reinterpret_cast<float2*>(C + (size_t)r0 * DMODEL + col) = v0;
            *reinterpret_cast<float2*>(C + (size_t)(r0 + 8) * DMODEL + col) = v1;
        }
    }
}

// ---------------------------------------------------------------------------
// Banded causal attention (11-wide). One block per (b,i); warp h = head h.
// Emits ctx as bf16 hi/lo for the O projection.
// ---------------------------------------------------------------------------
__global__ __launch_bounds__(256) void attn_banded(
    const float* __restrict__ Q, const float* __restrict__ K,
    const float* __restrict__ V, const float* __restrict__ td,
    __nv_bfloat16* __restrict__ chi, __nv_bfloat16* __restrict__ clo,
    float* __restrict__ attn_mean)
{
    const int bi = blockIdx.x;
    const int b  = bi >> 11;
    const int i  = bi & (SEQ - 1);
    const int tid = threadIdx.x;
    const int h = tid >> 5;
    const int l = tid & 31;

    __shared__ float s_d[MAXLAG + 1];
    __shared__ float s_attn[NHEADS][MAXLAG + 1];

    if (tid <= MAXLAG) {
        float x = td[tid];
        float sp = (x > 20.f) ? x : log1pf(expf(x));
        s_d[tid] = -logf(sp + 1e-8f);
    }
    __syncthreads();

    const int jstart = (i > MAXLAG) ? (i - MAXLAG) : 0;
    const int nj = i - jstart + 1;

    const float2* qp = reinterpret_cast<const float2*>(Q + (size_t)bi * DMODEL + h * HDIM);
    const float2 q2 = qp[l];

    float sc[MAXLAG + 1];
#pragma unroll
    for (int jj = 0; jj <= MAXLAG; jj++) {
        if (jj < nj) {
            const int j = jstart + jj;
            const float2* kp = reinterpret_cast<const float2*>(
                K + ((size_t)b * SEQ + j) * DMODEL + h * HDIM);
            const float2 k2 = kp[l];
            float dot = q2.x * k2.x + q2.y * k2.y;
#pragma unroll
            for (int off = 16; off; off >>= 1)
                dot += __shfl_xor_sync(0xffffffffu, dot, off);
            sc[jj] = dot * 0.125f + s_d[i - j];
        } else {
            sc[jj] = -1e30f;
        }
    }

    float mx = sc[0];
#pragma unroll
    for (int jj = 1; jj <= MAXLAG; jj++) mx = fmaxf(mx, sc[jj]);
    float sum = 0.f;
#pragma unroll
    for (int jj = 0; jj <= MAXLAG; jj++) {
        sc[jj] = expf(sc[jj] - mx);
        sum += sc[jj];
    }
    const float inv = 1.f / sum;

    float c0 = 0.f, c1 = 0.f;
#pragma unroll
    for (int jj = 0; jj <= MAXLAG; jj++) {
        if (jj < nj) {
            const float p = sc[jj] * inv;
            const int j = jstart + jj;
            const float2* vp = reinterpret_cast<const float2*>(
                V + ((size_t)b * SEQ + j) * DMODEL + h * HDIM);
            const float2 v2 = vp[l];
            c0 = fmaf(p, v2.x, c0);
            c1 = fmaf(p, v2.y, c1);
            if (l == 0) s_attn[h][jj] = p;
        }
    }

    __nv_bfloat162 hv, lv;
    split2(c0, c1, hv, lv);
    const size_t cidx = ((size_t)bi * DMODEL + h * HDIM) / 2 + l;
    reinterpret_cast<__nv_bfloat162*>(chi)[cidx] = hv;
    reinterpret_cast<__nv_bfloat162*>(clo)[cidx] = lv;

    __syncthreads();
    if (tid < nj) {
        float a = 0.f;
#pragma unroll
        for (int hh = 0; hh < NHEADS; hh++) a += s_attn[hh][tid];
        attn_mean[(size_t)b * SEQ * SEQ + (size_t)i * SEQ + jstart + tid] = a * (1.f / NHEADS);
    }
}

// ---------------------------------------------------------------------------
extern "C" void kernel_launch(void* const* d_in, const int* in_sizes, int n_in,
                              void* d_out, int out_size)
{
    const float* x  = (const float*)d_in[0];
    const float* Wq = (const float*)d_in[1];
    const float* bq = (const float*)d_in[2];
    const float* Wk = (const float*)d_in[3];
    const float* bk = (const float*)d_in[4];
    const float* Wv = (const float*)d_in[5];
    const float* bv = (const float*)d_in[6];
    const float* Wo = (const float*)d_in[7];
    const float* bo = (const float*)d_in[8];
    const float* td = (const float*)d_in[9];

    float* out_ptr  = (float*)d_out;
    float* attn_ptr = out_ptr + (size_t)BATCH * SEQ * DMODEL;

    __nv_bfloat16 *Xhi, *Xlo, *Chi, *Clo, *WT;
    float *Qs, *Ks, *Vs;
    cudaGetSymbolAddress((void**)&Xhi, g_Xhi);
    cudaGetSymbolAddress((void**)&Xlo, g_Xlo);
    cudaGetSymbolAddress((void**)&Chi, g_Chi);
    cudaGetSymbolAddress((void**)&Clo, g_Clo);
    cudaGetSymbolAddress((void**)&WT,  g_WT);
    cudaGetSymbolAddress((void**)&Qs,  g_Q);
    cudaGetSymbolAddress((void**)&Ks,  g_K);
    cudaGetSymbolAddress((void**)&Vs,  g_V);

    const size_t WSZ = (size_t)DMODEL * DMODEL;
    __nv_bfloat16* WqH = WT + 0 * WSZ; __nv_bfloat16* WqL = WT + 1 * WSZ;
    __nv_bfloat16* WkH = WT + 2 * WSZ; __nv_bfloat16* WkL = WT + 3 * WSZ;
    __nv_bfloat16* WvH = WT + 4 * WSZ; __nv_bfloat16* WvL = WT + 5 * WSZ;
    __nv_bfloat16* WoH = WT + 6 * WSZ; __nv_bfloat16* WoL = WT + 7 * WSZ;

    cudaFuncSetAttribute(gemm_bf16x3,
                         cudaFuncAttributeMaxDynamicSharedMemorySize, GSMEM_DYN);

    // 1) operand conversion
    convert_split<<<(MTOT * DMODEL / 4 + 255) / 256, 256>>>(x, Xhi, Xlo, MTOT * DMODEL / 4);
    dim3 wt(32, 8), wg(DMODEL / 32, DMODEL / 32);
    wsplitT<<<wg, wt>>>(Wq, WqH, WqL);
    wsplitT<<<wg, wt>>>(Wk, WkH, WkL);
    wsplitT<<<wg, wt>>>(Wv, WvH, WvL);
    wsplitT<<<wg, wt>>>(Wo, WoH, WoL);

    // 2) Q/K/V projections on tensor cores
    dim3 gg(DMODEL / 128, MTOT / 128);   // (4, 64)
    gemm_bf16x3<<<gg, 256, GSMEM_DYN>>>(Xhi, Xlo, WqH, WqL, bq, Qs);
    gemm_bf16x3<<<gg, 256, GSMEM_DYN>>>(Xhi, Xlo, WkH, WkL, bk, Ks);
    gemm_bf16x3<<<gg, 256, GSMEM_DYN>>>(Xhi, Xlo, WvH, WvL, bv, Vs);

    // 3) attn_mean zero + banded attention (writes ctx hi/lo)
    cudaMemsetAsync(attn_ptr, 0, (size_t)BATCH * SEQ * SEQ * sizeof(float), 0);
    attn_banded<<<MTOT, 256>>>(Qs, Ks, Vs, td, Chi, Clo, attn_ptr);

    // 4) O projection straight into d_out
    gemm_bf16x3<<<gg, 256, GSMEM_DYN>>>(Chi, Clo, WoH, WoL, bo, out_ptr);
}